// round 16
// baseline (speedup 1.0000x reference)
#include <cuda_runtime.h>
#include <cuda_fp16.h>

// ---------------------------------------------------------------------------
// VQ forward. Output: [loss(1) | quantized(N*256) | perp(1) | enc(N*K)]
// ---------------------------------------------------------------------------
#define NTOK   (64 * 2048)         // 131072
#define DDIM   256
#define KCODE  1024
#define QOFF   1
#define PERPOFF (1 + NTOK * DDIM)
#define ENCOFF  (PERPOFF + 1)

typedef unsigned long long u64;
typedef unsigned int u32;

// scratch (static device globals)
__device__ float  g_enorm[KCODE];
__device__ int    g_idx[NTOK];
__device__ int    g_cnt[KCODE];
__device__ double g_loss;
__device__ __align__(16) u32 g_Eh16[KCODE * 128];   // fp16x2 high limbs of emb
__device__ __align__(16) u32 g_El16[KCODE * 128];   // fp16x2 low  limbs of emb
__device__ __align__(16) u32 g_Wh16[DDIM * 128];    // fp16x2 high limbs of pre_w
__device__ __align__(16) u32 g_Wl16[DDIM * 128];    // fp16x2 low  limbs of pre_w

__device__ __forceinline__ u32 pkh(__half a, __half b) {
    return (u32)__half_as_ushort(a) | ((u32)__half_as_ushort(b) << 16);
}

// ---- mma.sync m16n8k16 f16 -> f32 (plain sm_80+ PTX) ----------------------
__device__ __forceinline__ void mma16816(float* c, u32 a0, u32 a1, u32 a2, u32 a3,
                                         u32 b0, u32 b1) {
    asm volatile(
        "mma.sync.aligned.m16n8k16.row.col.f32.f16.f16.f32 "
        "{%0,%1,%2,%3}, {%4,%5,%6,%7}, {%8,%9}, {%0,%1,%2,%3};"
        : "+f"(c[0]), "+f"(c[1]), "+f"(c[2]), "+f"(c[3])
        : "r"(a0), "r"(a1), "r"(a2), "r"(a3), "r"(b0), "r"(b1));
}

// ---- shared-memory layout (per 64-token CTA; 2 CTAs/SM) -------------------
#define OFF_F2     0                     // 256 floats: per-ch f2 partials
#define OFF_EN     1024                  // 256 floats (bias, then enorm 2x128)
#define OFF_BV     2048                  // 256 floats (argmin values, 4 ch)
#define OFF_BI     3072                  // 256 ints
#define OFF_A      4096                  // Fh: 64 rows x 132 u32 pitch
#define A_BYTES    (64 * 132 * 4)        // 33792
#define OFF_AL     (OFF_A + A_BYTES)
#define OFF_BST    (OFF_AL + A_BYTES)    // 71680: staging (40960 B)
#define BST_LIMB_W 2560                  // 128 codes x 20 u32 pitch (32 k-chunk)
#define BST_BUF_W  (2 * BST_LIMB_W)      // 5120 u32 per buffer
#define SMEM_TOTAL (OFF_BST + 2 * BST_BUF_W * 4)   // 112640 B

// ---------------------------------------------------------------------------
// Main fused kernel. CTA = 64 tokens, 256 threads (8 warps), 2 CTAs/SM.
// Warp grid 2x4: wg = wrp&1 -> rows [wg*32,+32), ch = wrp>>1 -> cols
// [ch*32,+32) of each 128-wide N tile. Stage = 32 k-elements.
// ---------------------------------------------------------------------------
__global__ void __launch_bounds__(256, 2)
vq_main(const float* __restrict__ x, const float* __restrict__ bias) {
    extern __shared__ char smc[];
    float* f2_s = (float*)(smc + OFF_F2);
    float* en_s = (float*)(smc + OFF_EN);
    float* bv_s = (float*)(smc + OFF_BV);
    int*   bi_s = (int*)(smc + OFF_BI);
    u32*   Fh   = (u32*)(smc + OFF_A);
    u32*   Fl   = (u32*)(smc + OFF_AL);
    u32*   Bst  = (u32*)(smc + OFF_BST);

    const int tid = threadIdx.x;
    const int lane = tid & 31, wrp = tid >> 5;
    const int g4 = lane >> 2, t4 = lane & 3;
    const int wg = wrp & 1, ch = wrp >> 1;
    const int rowA = wg * 32 + g4;          // m-tile 0 row; m-tile 1 adds 16
    const int row0 = blockIdx.x * 64;

    en_s[tid] = bias[tid];                  // bias for GEMM1 epilogue

    // ================= phase 1: HMMA pre-linear ============================
    // staging (single-buffered): Axh(64x20) | Axl | Bwh(128x20) | Bwl
    u32* Axh = Bst;
    u32* Axl = Bst + 1280;
    u32* Bwh = Bst + 2560;
    u32* Bwl = Bst + 5120;

    const int r2 = tid >> 2, eh2 = tid & 3;   // x copy: row 0..63, quarter
    const int er = tid >> 1, eh = tid & 1;    // E/W copy: code 0..127, half
    const uint4* WH = (const uint4*)g_Wh16;
    const uint4* WL = (const uint4*)g_Wl16;

    float4 xr[2]; uint4 pw[4];
    {   // prologue: stage 0 (nn2=0, kc2=0)
        const float4* xs = (const float4*)(x + (size_t)(row0 + r2) * DDIM + eh2 * 8);
        xr[0] = xs[0]; xr[1] = xs[1];
        size_t wb = (size_t)er * 32 + eh * 2;
        pw[0] = WH[wb]; pw[1] = WH[wb + 1];
        pw[2] = WL[wb]; pw[3] = WL[wb + 1];
    }

    float accf[32];
#pragma unroll
    for (int i = 0; i < 32; i++) accf[i] = 0.0f;
    float rs[4] = {0.0f, 0.0f, 0.0f, 0.0f};

#pragma unroll 1
    for (int s = 0; s < 16; s++) {
        const int nn2 = s >> 3;
        __syncthreads();               // previous MMAs done reading buffers
        // store x chunk (fp32 regs -> fp16 limbs) and W chunk
        {
            float4 v = xr[0], w = xr[1];
            __half hx = __float2half_rn(v.x), hy = __float2half_rn(v.y);
            __half hz = __float2half_rn(v.z), hw = __float2half_rn(v.w);
            __half gx = __float2half_rn(w.x), gy = __float2half_rn(w.y);
            __half gz = __float2half_rn(w.z), gw = __float2half_rn(w.w);
            uint4 H = make_uint4(pkh(hx, hy), pkh(hz, hw), pkh(gx, gy), pkh(gz, gw));
            uint4 L = make_uint4(
                pkh(__float2half_rn(v.x - __half2float(hx)),
                    __float2half_rn(v.y - __half2float(hy))),
                pkh(__float2half_rn(v.z - __half2float(hz)),
                    __float2half_rn(v.w - __half2float(hw))),
                pkh(__float2half_rn(w.x - __half2float(gx)),
                    __float2half_rn(w.y - __half2float(gy))),
                pkh(__float2half_rn(w.z - __half2float(gz)),
                    __float2half_rn(w.w - __half2float(gw))));
            *(uint4*)(Axh + r2 * 20 + eh2 * 4) = H;
            *(uint4*)(Axl + r2 * 20 + eh2 * 4) = L;
            uint4* wdh = (uint4*)(Bwh + er * 20 + eh * 8);
            uint4* wdl = (uint4*)(Bwl + er * 20 + eh * 8);
            wdh[0] = pw[0]; wdh[1] = pw[1];
            wdl[0] = pw[2]; wdl[1] = pw[3];
        }
        __syncthreads();
        // prefetch next stage into regs
        if (s < 15) {
            int ns = s + 1, nn = ns >> 3, nk = ns & 7;
            const float4* xs = (const float4*)(x + (size_t)(row0 + r2) * DDIM
                                               + nk * 32 + eh2 * 8);
            xr[0] = xs[0]; xr[1] = xs[1];
            size_t wb = (size_t)(nn * 128 + er) * 32 + nk * 4 + eh * 2;
            pw[0] = WH[wb]; pw[1] = WH[wb + 1];
            pw[2] = WL[wb]; pw[3] = WL[wb + 1];
        }
        // MMAs: B frags in regs, reused across both m-tiles
#pragma unroll
        for (int kk = 0; kk < 2; kk++) {
            u32 bhr[8], blr[8];
#pragma unroll
            for (int j = 0; j < 4; j++) {
                int bidx = ((ch * 4 + j) * 8 + g4) * 20 + kk * 8 + t4;
                bhr[j * 2] = Bwh[bidx]; bhr[j * 2 + 1] = Bwh[bidx + 4];
                blr[j * 2] = Bwl[bidx]; blr[j * 2 + 1] = Bwl[bidx + 4];
            }
#pragma unroll
            for (int mt = 0; mt < 2; mt++) {
                int a0i = (rowA + mt * 16) * 20 + kk * 8 + t4;
                int a1i = a0i + 8 * 20;
                u32 ah0 = Axh[a0i], ah1 = Axh[a1i], ah2 = Axh[a0i + 4], ah3 = Axh[a1i + 4];
                u32 al0 = Axl[a0i], al1 = Axl[a1i], al2 = Axl[a0i + 4], al3 = Axl[a1i + 4];
#pragma unroll
                for (int j = 0; j < 4; j++) {
                    float* c = accf + (mt * 4 + j) * 4;
                    mma16816(c, ah0, ah1, ah2, ah3, bhr[j * 2], bhr[j * 2 + 1]);
                    mma16816(c, ah0, ah1, ah2, ah3, blr[j * 2], blr[j * 2 + 1]);
                    mma16816(c, al0, al1, al2, al3, bhr[j * 2], bhr[j * 2 + 1]);
                }
            }
        }
        // tile epilogue: bias, ||f||^2 partials, limb split -> Fh/Fl
        if ((s & 7) == 7) {
#pragma unroll
            for (int mt = 0; mt < 2; mt++) {
                int rA = rowA + mt * 16;
#pragma unroll
                for (int j = 0; j < 4; j++) {
                    float* c = accf + (mt * 4 + j) * 4;
                    int col = nn2 * 128 + ch * 32 + j * 8 + 2 * t4;
                    float b0f = en_s[col], b1f = en_s[col + 1];
                    float v0 = c[0] + b0f, v1 = c[1] + b1f;
                    float v2 = c[2] + b0f, v3 = c[3] + b1f;
                    rs[mt * 2 + 0] = __fmaf_rn(v0, v0, rs[mt * 2 + 0]);
                    rs[mt * 2 + 0] = __fmaf_rn(v1, v1, rs[mt * 2 + 0]);
                    rs[mt * 2 + 1] = __fmaf_rn(v2, v2, rs[mt * 2 + 1]);
                    rs[mt * 2 + 1] = __fmaf_rn(v3, v3, rs[mt * 2 + 1]);
                    __half h0 = __float2half_rn(v0), h1 = __float2half_rn(v1);
                    __half h2 = __float2half_rn(v2), h3 = __float2half_rn(v3);
                    int kp = nn2 * 64 + ch * 16 + j * 4 + t4;
                    int pA = rA * 132 + kp;
                    int pB = (rA + 8) * 132 + kp;
                    Fh[pA] = pkh(h0, h1);
                    Fl[pA] = pkh(__float2half_rn(v0 - __half2float(h0)),
                                 __float2half_rn(v1 - __half2float(h1)));
                    Fh[pB] = pkh(h2, h3);
                    Fl[pB] = pkh(__float2half_rn(v2 - __half2float(h2)),
                                 __float2half_rn(v3 - __half2float(h3)));
                    c[0] = 0.0f; c[1] = 0.0f; c[2] = 0.0f; c[3] = 0.0f;
                }
            }
        }
    }
    // ||f||^2 partials: reduce over the 4 t4 lanes, store per (ch, row)
#pragma unroll
    for (int o = 2; o; o >>= 1) {
#pragma unroll
        for (int i = 0; i < 4; i++)
            rs[i] += __shfl_xor_sync(0xffffffffu, rs[i], o);
    }
    if (t4 == 0) {
        f2_s[ch * 64 + rowA]      = rs[0];
        f2_s[ch * 64 + rowA + 8]  = rs[1];
        f2_s[ch * 64 + rowA + 16] = rs[2];
        f2_s[ch * 64 + rowA + 24] = rs[3];
    }
    __syncthreads();   // Fh/Fl + partials ready; staging + en_s now free

    // ================= phase 2: HMMA distance GEMM + argmin ================
    float bestv[4] = {3.4e38f, 3.4e38f, 3.4e38f, 3.4e38f};
    int   ib[4] = {0, 0, 0, 0};

    const uint4* EH4 = (const uint4*)g_Eh16;
    const uint4* EL4 = (const uint4*)g_El16;

    // f2 combine + prologue: stage chunk 0 into buffer 0, enorm tile 0
    uint4 pre[4];
    {
        if (tid < 64)
            f2_s[tid] = f2_s[tid] + f2_s[64 + tid] + f2_s[128 + tid] + f2_s[192 + tid];
        size_t bi = (size_t)er * 32 + eh * 2;  // nt=0, kc2=0
        pre[0] = EH4[bi]; pre[1] = EH4[bi + 1];
        pre[2] = EL4[bi]; pre[3] = EL4[bi + 1];
        u32* d0 = Bst + er * 20 + eh * 8;
        ((uint4*)d0)[0] = pre[0]; ((uint4*)d0)[1] = pre[1];
        u32* d1 = d0 + BST_LIMB_W;
        ((uint4*)d1)[0] = pre[2]; ((uint4*)d1)[1] = pre[3];
        if (tid < 128) en_s[tid] = g_enorm[tid];
    }
    __syncthreads();
    float f2r[4];
#pragma unroll
    for (int mt = 0; mt < 2; mt++) {
        f2r[mt * 2 + 0] = f2_s[rowA + mt * 16];
        f2r[mt * 2 + 1] = f2_s[rowA + mt * 16 + 8];
    }

#pragma unroll 1
    for (int s = 0; s < 64; s++) {
        const int nt = s >> 3, kc2 = s & 7, buf = s & 1;
        // prefetch next chunk
        if (s < 63) {
            int nn = (s + 1) >> 3, nk = (s + 1) & 7;
            size_t bi = (size_t)(nn * 128 + er) * 32 + nk * 4 + eh * 2;
            pre[0] = EH4[bi]; pre[1] = EH4[bi + 1];
            pre[2] = EL4[bi]; pre[3] = EL4[bi + 1];
        }
        float enx = 0.0f;
        if (kc2 == 7 && nt < 7 && tid < 128) enx = g_enorm[(nt + 1) * 128 + tid];

        // MMAs on current buffer: (Fh,Bh) + (Fh,Bl) + (Fl,Bh)
        const u32* bh = Bst + buf * BST_BUF_W;
        const u32* bl = bh + BST_LIMB_W;
#pragma unroll
        for (int kk = 0; kk < 2; kk++) {
            u32 bhr[8], blr[8];
#pragma unroll
            for (int j = 0; j < 4; j++) {
                int bidx = ((ch * 4 + j) * 8 + g4) * 20 + kk * 8 + t4;
                bhr[j * 2] = bh[bidx]; bhr[j * 2 + 1] = bh[bidx + 4];
                blr[j * 2] = bl[bidx]; blr[j * 2 + 1] = bl[bidx + 4];
            }
#pragma unroll
            for (int mt = 0; mt < 2; mt++) {
                int a0i = (rowA + mt * 16) * 132 + kc2 * 16 + kk * 8 + t4;
                int a1i = a0i + 8 * 132;
                u32 ah0 = Fh[a0i], ah1 = Fh[a1i], ah2 = Fh[a0i + 4], ah3 = Fh[a1i + 4];
                u32 al0 = Fl[a0i], al1 = Fl[a1i], al2 = Fl[a0i + 4], al3 = Fl[a1i + 4];
#pragma unroll
                for (int j = 0; j < 4; j++) {
                    float* c = accf + (mt * 4 + j) * 4;
                    mma16816(c, ah0, ah1, ah2, ah3, bhr[j * 2], bhr[j * 2 + 1]);
                    mma16816(c, ah0, ah1, ah2, ah3, blr[j * 2], blr[j * 2 + 1]);
                    mma16816(c, al0, al1, al2, al3, bhr[j * 2], bhr[j * 2 + 1]);
                }
            }
        }
        // store prefetched chunk into the other buffer
        if (s < 63) {
            u32* d0 = Bst + (buf ^ 1) * BST_BUF_W + er * 20 + eh * 8;
            ((uint4*)d0)[0] = pre[0]; ((uint4*)d0)[1] = pre[1];
            u32* d1 = d0 + BST_LIMB_W;
            ((uint4*)d1)[0] = pre[2]; ((uint4*)d1)[1] = pre[3];
        }
        if (kc2 == 7 && nt < 7 && tid < 128)
            en_s[((nt + 1) & 1) * 128 + tid] = enx;
        __syncthreads();

        // per-N-tile argmin epilogue (regs only)
        if (kc2 == 7) {
            const float* ens = en_s + (nt & 1) * 128;
#pragma unroll
            for (int mt = 0; mt < 2; mt++) {
#pragma unroll
                for (int j = 0; j < 4; j++) {
                    float* c = accf + (mt * 4 + j) * 4;
                    int cl = ch * 32 + j * 8 + 2 * t4;
                    float e0 = ens[cl], e1 = ens[cl + 1];
                    int col = nt * 128 + cl;
                    float d;
                    d = __fsub_rn(__fadd_rn(f2r[mt * 2], e0), __fmul_rn(2.0f, c[0]));
                    if (d < bestv[mt * 2]) { bestv[mt * 2] = d; ib[mt * 2] = col; }
                    d = __fsub_rn(__fadd_rn(f2r[mt * 2], e1), __fmul_rn(2.0f, c[1]));
                    if (d < bestv[mt * 2]) { bestv[mt * 2] = d; ib[mt * 2] = col + 1; }
                    d = __fsub_rn(__fadd_rn(f2r[mt * 2 + 1], e0), __fmul_rn(2.0f, c[2]));
                    if (d < bestv[mt * 2 + 1]) { bestv[mt * 2 + 1] = d; ib[mt * 2 + 1] = col; }
                    d = __fsub_rn(__fadd_rn(f2r[mt * 2 + 1], e1), __fmul_rn(2.0f, c[3]));
                    if (d < bestv[mt * 2 + 1]) { bestv[mt * 2 + 1] = d; ib[mt * 2 + 1] = col + 1; }
                    c[0] = 0.0f; c[1] = 0.0f; c[2] = 0.0f; c[3] = 0.0f;
                }
            }
        }
    }

    // reduce argmin across the 4 t4-lanes (first-index ties), then across
    // the 4 column warps via smem
#pragma unroll
    for (int o = 2; o; o >>= 1) {
#pragma unroll
        for (int i = 0; i < 4; i++) {
            float ov = __shfl_xor_sync(0xffffffffu, bestv[i], o);
            int   oi = __shfl_xor_sync(0xffffffffu, ib[i], o);
            if (ov < bestv[i] || (ov == bestv[i] && oi < ib[i])) {
                bestv[i] = ov; ib[i] = oi;
            }
        }
    }
    if (t4 == 0) {
#pragma unroll
        for (int mt = 0; mt < 2; mt++) {
            bv_s[ch * 64 + rowA + mt * 16]     = bestv[mt * 2];
            bi_s[ch * 64 + rowA + mt * 16]     = ib[mt * 2];
            bv_s[ch * 64 + rowA + mt * 16 + 8] = bestv[mt * 2 + 1];
            bi_s[ch * 64 + rowA + mt * 16 + 8] = ib[mt * 2 + 1];
        }
    }
    __syncthreads();
    if (tid < 64) {
        float v = bv_s[tid];
        int   ix = bi_s[tid];
#pragma unroll
        for (int c = 1; c < 4; c++) {
            float vc = bv_s[c * 64 + tid];
            int   ic = bi_s[c * 64 + tid];
            if (vc < v || (vc == v && ic < ix)) { v = vc; ix = ic; }
        }
        g_idx[row0 + tid] = ix;
        atomicAdd(&g_cnt[ix], 1);
    }
}

// ---------------------------------------------------------------------------
// Small kernels
// ---------------------------------------------------------------------------
__global__ void init_k() {
    int t = threadIdx.x;
    if (t < KCODE) g_cnt[t] = 0;
    if (t == 0) g_loss = 0.0;
}

// limb split: blocks [0,KCODE) -> E (+enorm), [KCODE,KCODE+DDIM) -> W rows.
__global__ void prep_k(const float* __restrict__ E, const float* __restrict__ W) {
    __shared__ float red[4];
    int b = blockIdx.x, t = threadIdx.x;
    if (b < KCODE) {
        float v0 = E[(size_t)b * DDIM + 2 * t];
        float v1 = E[(size_t)b * DDIM + 2 * t + 1];
        __half h0 = __float2half_rn(v0);
        __half l0 = __float2half_rn(v0 - __half2float(h0));
        __half h1 = __float2half_rn(v1);
        __half l1 = __float2half_rn(v1 - __half2float(h1));
        g_Eh16[b * 128 + t] = pkh(h0, h1);
        g_El16[b * 128 + t] = pkh(l0, l1);
        float s = v0 * v0 + v1 * v1;
#pragma unroll
        for (int o = 16; o; o >>= 1) s += __shfl_xor_sync(0xffffffffu, s, o);
        if ((t & 31) == 0) red[t >> 5] = s;
        __syncthreads();
        if (t == 0) g_enorm[b] = red[0] + red[1] + red[2] + red[3];
    } else {
        int k2 = b - KCODE;
        float v0 = W[(size_t)k2 * DDIM + 2 * t];
        float v1 = W[(size_t)k2 * DDIM + 2 * t + 1];
        __half h0 = __float2half_rn(v0);
        __half l0 = __float2half_rn(v0 - __half2float(h0));
        __half h1 = __float2half_rn(v1);
        __half l1 = __float2half_rn(v1 - __half2float(h1));
        g_Wh16[k2 * 128 + t] = pkh(h0, h1);
        g_Wl16[k2 * 128 + t] = pkh(l0, l1);
    }
}

// fused one-hot writer: one warp per token writes its full 1024-float row
__global__ void enc_k(float* __restrict__ out) {
    int tok = (blockIdx.x * blockDim.x + threadIdx.x) >> 5;
    int lane = threadIdx.x & 31;
    if (tok >= NTOK) return;
    int idx = g_idx[tok];
    float2* row = reinterpret_cast<float2*>(out + ENCOFF + (size_t)tok * KCODE);
#pragma unroll
    for (int q = 0; q < 16; q++) {
        int p = q * 32 + lane;
        float2 v;
        v.x = (2 * p     == idx) ? 1.0f : 0.0f;
        v.y = (2 * p + 1 == idx) ? 1.0f : 0.0f;
        row[p] = v;
    }
}

__global__ void quant_loss(float* __restrict__ out, const float* __restrict__ x,
                           const float* __restrict__ E) {
    int warp = (blockIdx.x * blockDim.x + threadIdx.x) >> 5;
    int lane = threadIdx.x & 31;
    if (warp >= NTOK) return;
    int c = g_idx[warp];
    const float4* e4 = reinterpret_cast<const float4*>(E + (size_t)c * DDIM);
    const float4* x4 = reinterpret_cast<const float4*>(x + (size_t)warp * DDIM);
    float4 e0 = e4[lane * 2], e1 = e4[lane * 2 + 1];
    float4 v0 = x4[lane * 2], v1 = x4[lane * 2 + 1];
    float* q = out + QOFF + (size_t)warp * DDIM + lane * 8;
    float s = 0.0f, d;
    d = __fsub_rn(e0.x, v0.x); q[0] = __fadd_rn(v0.x, d); s = __fmaf_rn(d, d, s);
    d = __fsub_rn(e0.y, v0.y); q[1] = __fadd_rn(v0.y, d); s = __fmaf_rn(d, d, s);
    d = __fsub_rn(e0.z, v0.z); q[2] = __fadd_rn(v0.z, d); s = __fmaf_rn(d, d, s);
    d = __fsub_rn(e0.w, v0.w); q[3] = __fadd_rn(v0.w, d); s = __fmaf_rn(d, d, s);
    d = __fsub_rn(e1.x, v1.x); q[4] = __fadd_rn(v1.x, d); s = __fmaf_rn(d, d, s);
    d = __fsub_rn(e1.y, v1.y); q[5] = __fadd_rn(v1.y, d); s = __fmaf_rn(d, d, s);
    d = __fsub_rn(e1.z, v1.z); q[6] = __fadd_rn(v1.z, d); s = __fmaf_rn(d, d, s);
    d = __fsub_rn(e1.w, v1.w); q[7] = __fadd_rn(v1.w, d); s = __fmaf_rn(d, d, s);
#pragma unroll
    for (int o = 16; o; o >>= 1) s += __shfl_xor_sync(0xffffffffu, s, o);
    if (lane == 0) atomicAdd(&g_loss, (double)s);
}

__global__ void final_k(float* __restrict__ out) {
    __shared__ double red[32];
    int t = threadIdx.x;
    double p = (double)g_cnt[t] / (double)NTOK;
    double v = p * log(p + 1e-10);
#pragma unroll
    for (int o = 16; o; o >>= 1) v += __shfl_xor_sync(0xffffffffu, v, o);
    if ((t & 31) == 0) red[t >> 5] = v;
    __syncthreads();
    if (t < 32) {
        double w = red[t];
#pragma unroll
        for (int o = 16; o; o >>= 1) w += __shfl_xor_sync(0xffffffffu, w, o);
        if (t == 0) {
            out[PERPOFF] = (float)exp(-w);
            out[0] = (float)(0.25 * g_loss / (double)((long long)NTOK * DDIM));
        }
    }
}

// ---------------------------------------------------------------------------
extern "C" void kernel_launch(void* const* d_in, const int* in_sizes, int n_in,
                              void* d_out, int out_size) {
    const float* x = (const float*)d_in[0];   // inputs  [64,2048,256]
    const float* W = (const float*)d_in[1];   // pre_w   [256,256]
    const float* b = (const float*)d_in[2];   // pre_b   [256]
    const float* E = (const float*)d_in[3];   // emb     [1024,256]
    float* out = (float*)d_out;

    cudaFuncSetAttribute(vq_main, cudaFuncAttributeMaxDynamicSharedMemorySize, SMEM_TOTAL);

    init_k<<<1, 1024>>>();
    prep_k<<<KCODE + DDIM, 128>>>(E, W);
    init_k<<<1, 1024>>>();   // idempotent; aligns vq_main to launch #4 for ncu
    vq_main<<<NTOK / 64, 256, SMEM_TOTAL>>>(x, b);
    enc_k<<<NTOK / 8, 256>>>(out);
    quant_loss<<<NTOK / 8, 256>>>(out, x, E);
    final_k<<<1, 1024>>>(out);
}

// round 17
// speedup vs baseline: 1.3813x; 1.3813x over previous
#include <cuda_runtime.h>
#include <cuda_fp16.h>

// ---------------------------------------------------------------------------
// VQ forward. Output: [loss(1) | quantized(N*256) | perp(1) | enc(N*K)]
// ---------------------------------------------------------------------------
#define NTOK   (64 * 2048)         // 131072
#define DDIM   256
#define KCODE  1024
#define QOFF   1
#define PERPOFF (1 + NTOK * DDIM)
#define ENCOFF  (PERPOFF + 1)

typedef unsigned long long u64;
typedef unsigned int u32;

// scratch (static device globals)
__device__ float  g_enorm[KCODE];
__device__ int    g_idx[NTOK];
__device__ int    g_cnt[KCODE];
__device__ double g_loss;
__device__ __align__(16) u32 g_Eh16[KCODE * 128];   // fp16x2 high limbs of emb
__device__ __align__(16) u32 g_El16[KCODE * 128];   // fp16x2 low  limbs of emb
__device__ __align__(16) u32 g_Wh16[DDIM * 128];    // fp16x2 high limbs of pre_w
__device__ __align__(16) u32 g_Wl16[DDIM * 128];    // fp16x2 low  limbs of pre_w

__device__ __forceinline__ u32 pkh(__half a, __half b) {
    return (u32)__half_as_ushort(a) | ((u32)__half_as_ushort(b) << 16);
}

// ---- mma.sync m16n8k16 f16 -> f32 (plain sm_80+ PTX) ----------------------
__device__ __forceinline__ void mma16816(float* c, u32 a0, u32 a1, u32 a2, u32 a3,
                                         u32 b0, u32 b1) {
    asm volatile(
        "mma.sync.aligned.m16n8k16.row.col.f32.f16.f16.f32 "
        "{%0,%1,%2,%3}, {%4,%5,%6,%7}, {%8,%9}, {%0,%1,%2,%3};"
        : "+f"(c[0]), "+f"(c[1]), "+f"(c[2]), "+f"(c[3])
        : "r"(a0), "r"(a1), "r"(a2), "r"(a3), "r"(b0), "r"(b1));
}

// ---- ldmatrix x4 (non-trans, b16) -----------------------------------------
__device__ __forceinline__ void ldsm4(u32& r0, u32& r1, u32& r2, u32& r3,
                                      u32 saddr) {
    asm volatile(
        "ldmatrix.sync.aligned.m8n8.x4.shared.b16 {%0,%1,%2,%3}, [%4];"
        : "=r"(r0), "=r"(r1), "=r"(r2), "=r"(r3) : "r"(saddr));
}

// ---- shared-memory layout (R15 config: 128 tokens, 512 thr, 1 CTA/SM) ----
#define OFF_F2     0                     // 512 floats (per-ch f2 partials)
#define OFF_EN     2048                  // 256 floats (bias, then enorm 2x128)
#define OFF_BV     3072                  // 512 floats (argmin values, 4 ch)
#define OFF_BI     5120                  // 512 ints
#define OFF_A      8192                  // Fh: 128 rows x 132 u32 pitch
#define A_BYTES    (128 * 132 * 4)       // 67584
#define OFF_AL     (OFF_A + A_BYTES)     // Fl
#define OFF_BST    (OFF_AL + A_BYTES)    // 143360: staging (73728 B)
#define BST_LIMB_W 4608                  // 128 x 36 u32
#define BST_BUF_W  (2 * BST_LIMB_W)      // 9216 u32 per buffer (phase 2)
#define SMEM_TOTAL (OFF_BST + 2 * BST_BUF_W * 4)   // 217088 B

// ---------------------------------------------------------------------------
// Main fused kernel. CTA = 128 tokens, 512 threads (16 warps), 1 CTA/SM.
// 4x4 warp grid: wg = wrp&3 -> rows [wg*32,+32), ch = wrp>>2 -> cols
// [ch*32,+32) of each 128-wide N tile. Fragment loads via ldmatrix.
// ---------------------------------------------------------------------------
__global__ void __launch_bounds__(512, 1)
vq_main(const float* __restrict__ x, const float* __restrict__ bias) {
    extern __shared__ char smc[];
    float* f2_s = (float*)(smc + OFF_F2);
    float* en_s = (float*)(smc + OFF_EN);
    float* bv_s = (float*)(smc + OFF_BV);
    int*   bi_s = (int*)(smc + OFF_BI);
    u32*   Fh   = (u32*)(smc + OFF_A);
    u32*   Fl   = (u32*)(smc + OFF_AL);
    u32*   Bst  = (u32*)(smc + OFF_BST);
    const u32 smb = (u32)__cvta_generic_to_shared(smc);

    const int tid = threadIdx.x;
    const int lane = tid & 31, wrp = tid >> 5;
    const int g4 = lane >> 2, t4 = lane & 3;
    const int wg = wrp & 3, ch = wrp >> 2;
    const int rowA = wg * 32 + g4;          // m-tile 0 row; m-tile 1 adds 16
    const int row0 = blockIdx.x * 128;

    // ldmatrix lane-address components
    const int q = lane >> 3, r8 = lane & 7;
    const int aRow = (q & 1) * 8 + r8;      // A: row offset within m16 tile
    const int kh4  = (q >> 1) * 4;          // A: k-half offset (u32)
    const int bN   = (q >> 1) * 8 + r8;     // B: n offset within j-pair
    const int bKh4 = (q & 1) * 4;           // B: k-half offset (u32)

    if (tid < 256) en_s[tid] = bias[tid];   // bias for GEMM1 epilogue

    // ================= phase 1: HMMA pre-linear ============================
    // staging sub-layout (single-buffered): Axh | Axl | Bwh | Bwl (pitch 36)
    u32* Axh = Bst;
    u32* Axl = Bst + 4608;
    u32* Bwh = Bst + 9216;
    u32* Bwl = Bst + 13824;
    const u32 sbAxh = smb + OFF_BST;
    const u32 sbAxl = sbAxh + 4608 * 4;
    const u32 sbBwh = sbAxh + 9216 * 4;
    const u32 sbBwl = sbAxh + 13824 * 4;

    const int r2 = tid >> 2, eh2 = tid & 3;   // row 0..127, quarter 0..3
    float4 xr[4]; uint4 pw[4];
    {   // prologue: stage 0 (nt2=0, kc=0)
        const float4* xs = (const float4*)(x + (size_t)(row0 + r2) * DDIM + eh2 * 16);
#pragma unroll
        for (int i = 0; i < 4; i++) xr[i] = xs[i];
        const uint4* WH = (const uint4*)g_Wh16;
        const uint4* WL = (const uint4*)g_Wl16;
        size_t wb = (size_t)r2 * 32 + eh2 * 2;
        pw[0] = WH[wb]; pw[1] = WH[wb + 1];
        pw[2] = WL[wb]; pw[3] = WL[wb + 1];
    }

    float accf[32];
#pragma unroll
    for (int i = 0; i < 32; i++) accf[i] = 0.0f;
    float rs[4] = {0.0f, 0.0f, 0.0f, 0.0f};

#pragma unroll 1
    for (int s = 0; s < 8; s++) {
        const int nt2 = s >> 2;
        __syncthreads();               // previous MMAs done reading buffers
        // store x chunk (fp32 regs -> fp16 limbs) and W chunk
        {
            u32* dh = Axh + r2 * 36 + eh2 * 8;
            u32* dl = Axl + r2 * 36 + eh2 * 8;
#pragma unroll
            for (int i = 0; i < 4; i++) {
                float4 v = xr[i];
                __half hx = __float2half_rn(v.x), hy = __float2half_rn(v.y);
                __half hz = __float2half_rn(v.z), hw = __float2half_rn(v.w);
                dh[2 * i]     = pkh(hx, hy);
                dh[2 * i + 1] = pkh(hz, hw);
                dl[2 * i]     = pkh(__float2half_rn(v.x - __half2float(hx)),
                                    __float2half_rn(v.y - __half2float(hy)));
                dl[2 * i + 1] = pkh(__float2half_rn(v.z - __half2float(hz)),
                                    __float2half_rn(v.w - __half2float(hw)));
            }
            uint4* wdh = (uint4*)(Bwh + r2 * 36 + eh2 * 8);
            uint4* wdl = (uint4*)(Bwl + r2 * 36 + eh2 * 8);
            wdh[0] = pw[0]; wdh[1] = pw[1];
            wdl[0] = pw[2]; wdl[1] = pw[3];
        }
        __syncthreads();
        // prefetch next stage into regs
        if (s < 7) {
            int ns = s + 1, nn2 = ns >> 2, nk = ns & 3;
            const float4* xs = (const float4*)(x + (size_t)(row0 + r2) * DDIM
                                               + nk * 64 + eh2 * 16);
#pragma unroll
            for (int i = 0; i < 4; i++) xr[i] = xs[i];
            const uint4* WH = (const uint4*)g_Wh16;
            const uint4* WL = (const uint4*)g_Wl16;
            size_t wb = (size_t)(nn2 * 128 + r2) * 32 + nk * 8 + eh2 * 2;
            pw[0] = WH[wb]; pw[1] = WH[wb + 1];
            pw[2] = WL[wb]; pw[3] = WL[wb + 1];
        }
        // MMAs with ldmatrix fragment loads
#pragma unroll
        for (int kk = 0; kk < 4; kk++) {
            u32 bfh[8], bfl[8];
#pragma unroll
            for (int jp = 0; jp < 2; jp++) {
                u32 boff = (u32)((ch * 32 + jp * 16 + bN) * 36 + kk * 8 + bKh4) * 4;
                ldsm4(bfh[jp * 4], bfh[jp * 4 + 1], bfh[jp * 4 + 2], bfh[jp * 4 + 3],
                      sbBwh + boff);
                ldsm4(bfl[jp * 4], bfl[jp * 4 + 1], bfl[jp * 4 + 2], bfl[jp * 4 + 3],
                      sbBwl + boff);
            }
#pragma unroll
            for (int mt = 0; mt < 2; mt++) {
                u32 aoff = (u32)((wg * 32 + mt * 16 + aRow) * 36 + kk * 8 + kh4) * 4;
                u32 ah0, ah1, ah2, ah3, al0, al1, al2, al3;
                ldsm4(ah0, ah1, ah2, ah3, sbAxh + aoff);
                ldsm4(al0, al1, al2, al3, sbAxl + aoff);
#pragma unroll
                for (int j = 0; j < 4; j++) {
                    int jp = j >> 1, jj = j & 1;
                    u32 b0 = bfh[jp * 4 + jj * 2], b1 = bfh[jp * 4 + jj * 2 + 1];
                    u32 c0 = bfl[jp * 4 + jj * 2], c1 = bfl[jp * 4 + jj * 2 + 1];
                    float* c = accf + (mt * 4 + j) * 4;
                    mma16816(c, ah0, ah1, ah2, ah3, b0, b1);
                    mma16816(c, ah0, ah1, ah2, ah3, c0, c1);
                    mma16816(c, al0, al1, al2, al3, b0, b1);
                }
            }
        }
        // tile epilogue: bias, ||f||^2 partials, limb split -> Fh/Fl
        if ((s & 3) == 3) {
#pragma unroll
            for (int mt = 0; mt < 2; mt++) {
                int rA = rowA + mt * 16;
#pragma unroll
                for (int j = 0; j < 4; j++) {
                    float* c = accf + (mt * 4 + j) * 4;
                    int col = nt2 * 128 + ch * 32 + j * 8 + 2 * t4;
                    float b0f = en_s[col], b1f = en_s[col + 1];
                    float v0 = c[0] + b0f, v1 = c[1] + b1f;
                    float v2 = c[2] + b0f, v3 = c[3] + b1f;
                    rs[mt * 2 + 0] = __fmaf_rn(v0, v0, rs[mt * 2 + 0]);
                    rs[mt * 2 + 0] = __fmaf_rn(v1, v1, rs[mt * 2 + 0]);
                    rs[mt * 2 + 1] = __fmaf_rn(v2, v2, rs[mt * 2 + 1]);
                    rs[mt * 2 + 1] = __fmaf_rn(v3, v3, rs[mt * 2 + 1]);
                    __half h0 = __float2half_rn(v0), h1 = __float2half_rn(v1);
                    __half h2 = __float2half_rn(v2), h3 = __float2half_rn(v3);
                    int kp = nt2 * 64 + ch * 16 + j * 4 + t4;
                    int pA = rA * 132 + kp;
                    int pB = (rA + 8) * 132 + kp;
                    Fh[pA] = pkh(h0, h1);
                    Fl[pA] = pkh(__float2half_rn(v0 - __half2float(h0)),
                                 __float2half_rn(v1 - __half2float(h1)));
                    Fh[pB] = pkh(h2, h3);
                    Fl[pB] = pkh(__float2half_rn(v2 - __half2float(h2)),
                                 __float2half_rn(v3 - __half2float(h3)));
                    c[0] = 0.0f; c[1] = 0.0f; c[2] = 0.0f; c[3] = 0.0f;
                }
            }
        }
    }
    // ||f||^2 partials: reduce over the 4 t4 lanes, store per (ch, row)
#pragma unroll
    for (int o = 2; o; o >>= 1) {
#pragma unroll
        for (int i = 0; i < 4; i++)
            rs[i] += __shfl_xor_sync(0xffffffffu, rs[i], o);
    }
    if (t4 == 0) {
        f2_s[ch * 128 + rowA]      = rs[0];
        f2_s[ch * 128 + rowA + 8]  = rs[1];
        f2_s[ch * 128 + rowA + 16] = rs[2];
        f2_s[ch * 128 + rowA + 24] = rs[3];
    }
    __syncthreads();   // Fh/Fl + partials ready; staging + en_s free
    if (tid < 128)
        f2_s[tid] = f2_s[tid] + f2_s[128 + tid] + f2_s[256 + tid] + f2_s[384 + tid];

    // ================= phase 2: HMMA distance GEMM + argmin ================
    float bestv[4] = {3.4e38f, 3.4e38f, 3.4e38f, 3.4e38f};
    int   ib[4] = {0, 0, 0, 0};

    const int er = tid >> 2, eh = tid & 3;     // stage-copy mapping
    const uint4* EH4 = (const uint4*)g_Eh16;
    const uint4* EL4 = (const uint4*)g_El16;

    // prologue: stage chunk 0 into buffer 0, stage enorm tile 0
    uint4 pre[4];
    {
        size_t bi = (size_t)er * 32 + eh * 2;  // nt=0, kc=0
        pre[0] = EH4[bi]; pre[1] = EH4[bi + 1];
        pre[2] = EL4[bi]; pre[3] = EL4[bi + 1];
        u32* d0 = Bst + er * 36 + eh * 8;
        ((uint4*)d0)[0] = pre[0]; ((uint4*)d0)[1] = pre[1];
        u32* d1 = d0 + BST_LIMB_W;
        ((uint4*)d1)[0] = pre[2]; ((uint4*)d1)[1] = pre[3];
        if (tid < 128) en_s[tid] = g_enorm[tid];
    }
    __syncthreads();
    float f2r[4];
#pragma unroll
    for (int mt = 0; mt < 2; mt++) {
        f2r[mt * 2 + 0] = f2_s[rowA + mt * 16];
        f2r[mt * 2 + 1] = f2_s[rowA + mt * 16 + 8];
    }

    const u32 sbFh = smb + OFF_A;
    const u32 sbFl = smb + OFF_AL;
    const u32 sbBst = smb + OFF_BST;

#pragma unroll 1
    for (int s = 0; s < 32; s++) {
        const int nt = s >> 2, kc = s & 3, buf = s & 1;
        // prefetch next chunk
        if (s < 31) {
            int nn = (s + 1) >> 2, nk = (s + 1) & 3;
            size_t bi = (size_t)(nn * 128 + er) * 32 + nk * 8 + eh * 2;
            pre[0] = EH4[bi]; pre[1] = EH4[bi + 1];
            pre[2] = EL4[bi]; pre[3] = EL4[bi + 1];
        }
        float enx = 0.0f;
        if (kc == 3 && nt < 7 && tid < 128) enx = g_enorm[(nt + 1) * 128 + tid];

        // MMAs on current buffer: (Fh,Bh) + (Fh,Bl) + (Fl,Bh)
        const u32 sbBh = sbBst + (u32)buf * BST_BUF_W * 4;
        const u32 sbBl = sbBh + BST_LIMB_W * 4;
#pragma unroll
        for (int kk = 0; kk < 4; kk++) {
            u32 bfh[8], bfl[8];
#pragma unroll
            for (int jp = 0; jp < 2; jp++) {
                u32 boff = (u32)((ch * 32 + jp * 16 + bN) * 36 + kk * 8 + bKh4) * 4;
                ldsm4(bfh[jp * 4], bfh[jp * 4 + 1], bfh[jp * 4 + 2], bfh[jp * 4 + 3],
                      sbBh + boff);
                ldsm4(bfl[jp * 4], bfl[jp * 4 + 1], bfl[jp * 4 + 2], bfl[jp * 4 + 3],
                      sbBl + boff);
            }
#pragma unroll
            for (int mt = 0; mt < 2; mt++) {
                u32 aoff = (u32)((wg * 32 + mt * 16 + aRow) * 132
                                 + kc * 32 + kk * 8 + kh4) * 4;
                u32 ah0, ah1, ah2, ah3, al0, al1, al2, al3;
                ldsm4(ah0, ah1, ah2, ah3, sbFh + aoff);
                ldsm4(al0, al1, al2, al3, sbFl + aoff);
#pragma unroll
                for (int j = 0; j < 4; j++) {
                    int jp = j >> 1, jj = j & 1;
                    u32 b0 = bfh[jp * 4 + jj * 2], b1 = bfh[jp * 4 + jj * 2 + 1];
                    u32 c0 = bfl[jp * 4 + jj * 2], c1 = bfl[jp * 4 + jj * 2 + 1];
                    float* c = accf + (mt * 4 + j) * 4;
                    mma16816(c, ah0, ah1, ah2, ah3, b0, b1);
                    mma16816(c, ah0, ah1, ah2, ah3, c0, c1);
                    mma16816(c, al0, al1, al2, al3, b0, b1);
                }
            }
        }
        // store prefetched chunk into the other buffer
        if (s < 31) {
            u32* d0 = Bst + (buf ^ 1) * BST_BUF_W + er * 36 + eh * 8;
            ((uint4*)d0)[0] = pre[0]; ((uint4*)d0)[1] = pre[1];
            u32* d1 = d0 + BST_LIMB_W;
            ((uint4*)d1)[0] = pre[2]; ((uint4*)d1)[1] = pre[3];
        }
        if (kc == 3 && nt < 7 && tid < 128)
            en_s[((nt + 1) & 1) * 128 + tid] = enx;
        __syncthreads();

        // per-N-tile argmin epilogue (regs only)
        if (kc == 3) {
            const float* ens = en_s + (nt & 1) * 128;
#pragma unroll
            for (int mt = 0; mt < 2; mt++) {
#pragma unroll
                for (int j = 0; j < 4; j++) {
                    float* c = accf + (mt * 4 + j) * 4;
                    int cl = ch * 32 + j * 8 + 2 * t4;
                    float e0 = ens[cl], e1 = ens[cl + 1];
                    int col = nt * 128 + cl;
                    float d;
                    d = __fsub_rn(__fadd_rn(f2r[mt * 2], e0), __fmul_rn(2.0f, c[0]));
                    if (d < bestv[mt * 2]) { bestv[mt * 2] = d; ib[mt * 2] = col; }
                    d = __fsub_rn(__fadd_rn(f2r[mt * 2], e1), __fmul_rn(2.0f, c[1]));
                    if (d < bestv[mt * 2]) { bestv[mt * 2] = d; ib[mt * 2] = col + 1; }
                    d = __fsub_rn(__fadd_rn(f2r[mt * 2 + 1], e0), __fmul_rn(2.0f, c[2]));
                    if (d < bestv[mt * 2 + 1]) { bestv[mt * 2 + 1] = d; ib[mt * 2 + 1] = col; }
                    d = __fsub_rn(__fadd_rn(f2r[mt * 2 + 1], e1), __fmul_rn(2.0f, c[3]));
                    if (d < bestv[mt * 2 + 1]) { bestv[mt * 2 + 1] = d; ib[mt * 2 + 1] = col + 1; }
                    c[0] = 0.0f; c[1] = 0.0f; c[2] = 0.0f; c[3] = 0.0f;
                }
            }
        }
    }

    // reduce argmin across the 4 t4-lanes (first-index ties), then across
    // the 4 column warps via smem
#pragma unroll
    for (int o = 2; o; o >>= 1) {
#pragma unroll
        for (int i = 0; i < 4; i++) {
            float ov = __shfl_xor_sync(0xffffffffu, bestv[i], o);
            int   oi = __shfl_xor_sync(0xffffffffu, ib[i], o);
            if (ov < bestv[i] || (ov == bestv[i] && oi < ib[i])) {
                bestv[i] = ov; ib[i] = oi;
            }
        }
    }
    if (t4 == 0) {
#pragma unroll
        for (int mt = 0; mt < 2; mt++) {
            bv_s[ch * 128 + rowA + mt * 16]     = bestv[mt * 2];
            bi_s[ch * 128 + rowA + mt * 16]     = ib[mt * 2];
            bv_s[ch * 128 + rowA + mt * 16 + 8] = bestv[mt * 2 + 1];
            bi_s[ch * 128 + rowA + mt * 16 + 8] = ib[mt * 2 + 1];
        }
    }
    __syncthreads();
    if (tid < 128) {
        float v = bv_s[tid];
        int   ix = bi_s[tid];
#pragma unroll
        for (int c = 1; c < 4; c++) {
            float vc = bv_s[c * 128 + tid];
            int   ic = bi_s[c * 128 + tid];
            if (vc < v || (vc == v && ic < ix)) { v = vc; ix = ic; }
        }
        g_idx[row0 + tid] = ix;
        atomicAdd(&g_cnt[ix], 1);
    }
}

// ---------------------------------------------------------------------------
// Small kernels
// ---------------------------------------------------------------------------
__global__ void init_k() {
    int t = threadIdx.x;
    if (t < KCODE) g_cnt[t] = 0;
    if (t == 0) g_loss = 0.0;
}

// limb split: blocks [0,KCODE) -> E (+enorm), [KCODE,KCODE+DDIM) -> W rows.
__global__ void prep_k(const float* __restrict__ E, const float* __restrict__ W) {
    __shared__ float red[4];
    int b = blockIdx.x, t = threadIdx.x;
    if (b < KCODE) {
        float v0 = E[(size_t)b * DDIM + 2 * t];
        float v1 = E[(size_t)b * DDIM + 2 * t + 1];
        __half h0 = __float2half_rn(v0);
        __half l0 = __float2half_rn(v0 - __half2float(h0));
        __half h1 = __float2half_rn(v1);
        __half l1 = __float2half_rn(v1 - __half2float(h1));
        g_Eh16[b * 128 + t] = pkh(h0, h1);
        g_El16[b * 128 + t] = pkh(l0, l1);
        float s = v0 * v0 + v1 * v1;
#pragma unroll
        for (int o = 16; o; o >>= 1) s += __shfl_xor_sync(0xffffffffu, s, o);
        if ((t & 31) == 0) red[t >> 5] = s;
        __syncthreads();
        if (t == 0) g_enorm[b] = red[0] + red[1] + red[2] + red[3];
    } else {
        int k2 = b - KCODE;
        float v0 = W[(size_t)k2 * DDIM + 2 * t];
        float v1 = W[(size_t)k2 * DDIM + 2 * t + 1];
        __half h0 = __float2half_rn(v0);
        __half l0 = __float2half_rn(v0 - __half2float(h0));
        __half h1 = __float2half_rn(v1);
        __half l1 = __float2half_rn(v1 - __half2float(h1));
        g_Wh16[k2 * 128 + t] = pkh(h0, h1);
        g_Wl16[k2 * 128 + t] = pkh(l0, l1);
    }
}

// fused one-hot writer: one warp per token writes its full 1024-float row
__global__ void enc_k(float* __restrict__ out) {
    int tok = (blockIdx.x * blockDim.x + threadIdx.x) >> 5;
    int lane = threadIdx.x & 31;
    if (tok >= NTOK) return;
    int idx = g_idx[tok];
    float2* row = reinterpret_cast<float2*>(out + ENCOFF + (size_t)tok * KCODE);
#pragma unroll
    for (int q = 0; q < 16; q++) {
        int p = q * 32 + lane;
        float2 v;
        v.x = (2 * p     == idx) ? 1.0f : 0.0f;
        v.y = (2 * p + 1 == idx) ? 1.0f : 0.0f;
        row[p] = v;
    }
}

__global__ void quant_loss(float* __restrict__ out, const float* __restrict__ x,
                           const float* __restrict__ E) {
    int warp = (blockIdx.x * blockDim.x + threadIdx.x) >> 5;
    int lane = threadIdx.x & 31;
    if (warp >= NTOK) return;
    int c = g_idx[warp];
    const float4* e4 = reinterpret_cast<const float4*>(E + (size_t)c * DDIM);
    const float4* x4 = reinterpret_cast<const float4*>(x + (size_t)warp * DDIM);
    float4 e0 = e4[lane * 2], e1 = e4[lane * 2 + 1];
    float4 v0 = x4[lane * 2], v1 = x4[lane * 2 + 1];
    float* q = out + QOFF + (size_t)warp * DDIM + lane * 8;
    float s = 0.0f, d;
    d = __fsub_rn(e0.x, v0.x); q[0] = __fadd_rn(v0.x, d); s = __fmaf_rn(d, d, s);
    d = __fsub_rn(e0.y, v0.y); q[1] = __fadd_rn(v0.y, d); s = __fmaf_rn(d, d, s);
    d = __fsub_rn(e0.z, v0.z); q[2] = __fadd_rn(v0.z, d); s = __fmaf_rn(d, d, s);
    d = __fsub_rn(e0.w, v0.w); q[3] = __fadd_rn(v0.w, d); s = __fmaf_rn(d, d, s);
    d = __fsub_rn(e1.x, v1.x); q[4] = __fadd_rn(v1.x, d); s = __fmaf_rn(d, d, s);
    d = __fsub_rn(e1.y, v1.y); q[5] = __fadd_rn(v1.y, d); s = __fmaf_rn(d, d, s);
    d = __fsub_rn(e1.z, v1.z); q[6] = __fadd_rn(v1.z, d); s = __fmaf_rn(d, d, s);
    d = __fsub_rn(e1.w, v1.w); q[7] = __fadd_rn(v1.w, d); s = __fmaf_rn(d, d, s);
#pragma unroll
    for (int o = 16; o; o >>= 1) s += __shfl_xor_sync(0xffffffffu, s, o);
    if (lane == 0) atomicAdd(&g_loss, (double)s);
}

__global__ void final_k(float* __restrict__ out) {
    __shared__ double red[32];
    int t = threadIdx.x;
    double p = (double)g_cnt[t] / (double)NTOK;
    double v = p * log(p + 1e-10);
#pragma unroll
    for (int o = 16; o; o >>= 1) v += __shfl_xor_sync(0xffffffffu, v, o);
    if ((t & 31) == 0) red[t >> 5] = v;
    __syncthreads();
    if (t < 32) {
        double w = red[t];
#pragma unroll
        for (int o = 16; o; o >>= 1) w += __shfl_xor_sync(0xffffffffu, w, o);
        if (t == 0) {
            out[PERPOFF] = (float)exp(-w);
            out[0] = (float)(0.25 * g_loss / (double)((long long)NTOK * DDIM));
        }
    }
}

// ---------------------------------------------------------------------------
extern "C" void kernel_launch(void* const* d_in, const int* in_sizes, int n_in,
                              void* d_out, int out_size) {
    const float* x = (const float*)d_in[0];   // inputs  [64,2048,256]
    const float* W = (const float*)d_in[1];   // pre_w   [256,256]
    const float* b = (const float*)d_in[2];   // pre_b   [256]
    const float* E = (const float*)d_in[3];   // emb     [1024,256]
    float* out = (float*)d_out;

    cudaFuncSetAttribute(vq_main, cudaFuncAttributeMaxDynamicSharedMemorySize, SMEM_TOTAL);

    init_k<<<1, 1024>>>();
    prep_k<<<KCODE + DDIM, 128>>>(E, W);
    init_k<<<1, 1024>>>();   // idempotent; aligns vq_main to launch #4 for ncu
    vq_main<<<NTOK / 128, 512, SMEM_TOTAL>>>(x, b);
    enc_k<<<NTOK / 8, 256>>>(out);
    quant_loss<<<NTOK / 8, 256>>>(out, x, E);
    final_k<<<1, 1024>>>(out);
}